// round 13
// baseline (speedup 1.0000x reference)
#include <cuda_runtime.h>
#include <cstdint>
#include <cstddef>

// ============================================================================
// EnhancedGNNEncoder: 2x GCNConv(+BN+ReLU) + GCNConv mu / GCNConv logstd
//   N=100000, E=3200000, dims 81 -> 64 -> 64 -> {32|32}
// R8 = R6 (387us) + branch-free padded gather:
//   - Buckets padded to multiple of 8 with index MAXN -> zero feature row.
//   - Agg inner loop: no data-dependent break; 4 LDG.128s batch per unrolled
//     group (higher MLP, less ALU). dis still uses true degree.
// ============================================================================

#define MAXN 100000
#define MAXE 3200000
#define BUCKET 96

__device__ int   g_cnt[MAXN];                    // per-node degree
__device__ int   g_srcs[(size_t)MAXN * BUCKET];  // bucketed adjacency (by dst)
__device__ float g_A[(size_t)(MAXN + 1) * 64];   // +1: zero row for padding
__device__ float g_B[(size_t)MAXN * 64];         // aggregation outputs (BN inputs)
__device__ float g_stats[2 * 128];               // per BN layer: sum(64) | sumsq(64)
__device__ int   g_is64;

// ---------------------------------------------------------------------------
// init: zero counters/stats/pad-row; block 0 probes edge dtype.
// ---------------------------------------------------------------------------
__global__ void k_init(const unsigned* __restrict__ p, int n) {
    int i = blockIdx.x * blockDim.x + threadIdx.x;
    if (i < n)   g_cnt[i] = 0;
    if (i < 256) g_stats[i] = 0.f;
    if (i < 64)  g_A[(size_t)MAXN * 64 + i] = 0.f;   // zero feature row
    if (blockIdx.x == 0) {
        unsigned acc = 0;
        for (int k = threadIdx.x; k < 2048; k += 256) acc |= p[2 * k + 1];
#pragma unroll
        for (int off = 16; off; off >>= 1) acc |= __shfl_xor_sync(0xffffffffu, acc, off);
        __shared__ unsigned w[8];
        if ((threadIdx.x & 31) == 0) w[threadIdx.x >> 5] = acc;
        __syncthreads();
        if (threadIdx.x == 0) {
            unsigned t = 0;
#pragma unroll
            for (int q = 0; q < 8; q++) t |= w[q];
            g_is64 = (t == 0) ? 1 : 0;
        }
    }
}

// ---------------------------------------------------------------------------
// fill: one pass. slot = atomicAdd(cnt[dst]); srcs[dst*96+slot] = src
// ---------------------------------------------------------------------------
__global__ void k_fill(const void* __restrict__ ei, int E) {
    int e = blockIdx.x * blockDim.x + threadIdx.x;
    if (e >= E) return;
    int s, d;
    if (g_is64) {
        s = (int)((const long long*)ei)[e];
        d = (int)((const long long*)ei)[(long long)E + e];
    } else {
        s = ((const int*)ei)[e];
        d = ((const int*)ei)[E + e];
    }
    int slot = atomicAdd(&g_cnt[d], 1);
    if (slot < BUCKET) g_srcs[(size_t)d * BUCKET + slot] = s;
}

// ---------------------------------------------------------------------------
// pad: fill slots cnt..ceil8(cnt) with MAXN (zero row) so agg is branch-free.
// ---------------------------------------------------------------------------
__global__ void k_pad(int n) {
    int i = blockIdx.x * blockDim.x + threadIdx.x;
    if (i >= n) return;
    int c = g_cnt[i]; if (c > BUCKET) c = BUCKET;
    int cp = (c + 7) & ~7; if (cp > BUCKET) cp = BUCKET;
    for (int s = c; s < cp; s++) g_srcs[(size_t)i * BUCKET + s] = MAXN;
}

// ---------------------------------------------------------------------------
// GEMM1: g_A[r] = dis[r] * (x[r,81] @ W1[81,64]). 4x4 register tiling.
// ---------------------------------------------------------------------------
__global__ void k_gemm81(const float* __restrict__ x, const float* __restrict__ W, int n) {
    __shared__ float Ws[81 * 64];
    __shared__ float Xs[81 * 68];   // [k][row], stride 68
    __shared__ float ds[64];
    const int t = threadIdx.x;          // 256
    const int r0b = blockIdx.x * 64;
    for (int i = t; i < 81 * 64; i += 256) Ws[i] = W[i];
    if (t < 64) {
        int r = r0b + t;
        ds[t] = (r < n) ? rsqrtf((float)(g_cnt[r] + 1)) : 0.f;
    }
    {
        size_t gbase = (size_t)r0b * 81;
        size_t lim = (size_t)n * 81;
        for (int i = t; i < 64 * 81; i += 256) {
            size_t g = gbase + i;
            float v = (g < lim) ? x[g] : 0.f;
            int row = i / 81, k = i - row * 81;
            Xs[k * 68 + row] = v;
        }
    }
    __syncthreads();
    const int lr = (t >> 4) * 4;
    const int c0 = (t & 15) * 4;
    float4 a0 = {0,0,0,0}, a1 = {0,0,0,0}, a2 = {0,0,0,0}, a3 = {0,0,0,0};
#pragma unroll 3
    for (int k = 0; k < 81; k++) {
        float4 xv = *(const float4*)&Xs[k * 68 + lr];
        float4 wv = *(const float4*)&Ws[k * 64 + c0];
        a0.x += xv.x * wv.x; a0.y += xv.x * wv.y; a0.z += xv.x * wv.z; a0.w += xv.x * wv.w;
        a1.x += xv.y * wv.x; a1.y += xv.y * wv.y; a1.z += xv.y * wv.z; a1.w += xv.y * wv.w;
        a2.x += xv.z * wv.x; a2.y += xv.z * wv.y; a2.z += xv.z * wv.z; a2.w += xv.z * wv.w;
        a3.x += xv.w * wv.x; a3.y += xv.w * wv.y; a3.z += xv.w * wv.z; a3.w += xv.w * wv.w;
    }
    float4 accs[4] = {a0, a1, a2, a3};
#pragma unroll
    for (int j = 0; j < 4; j++) {
        int r = r0b + lr + j;
        if (r < n) {
            float d = ds[lr + j];
            float4 o = accs[j];
            o.x *= d; o.y *= d; o.z *= d; o.w *= d;
            *(float4*)&g_A[(size_t)r * 64 + c0] = o;
        }
    }
}

// ---------------------------------------------------------------------------
// GEMM64: g_A[r] = dis[r] * (BNReLU(g_B)[r,64] @ W[64,64]); W = Wa or [Wa|Wb].
// ---------------------------------------------------------------------------
__global__ void k_gemm64(const float* __restrict__ Wa, const float* __restrict__ Wb,
                         const float* __restrict__ gamma, const float* __restrict__ beta,
                         int bnIdx, int n, float invn) {
    __shared__ float Ws[64 * 64];
    __shared__ float Xs[64 * 68];
    __shared__ float ssc[64], ssh[64], ds[64];
    const int t = threadIdx.x;          // 256
    const int r0b = blockIdx.x * 64;
    if (t < 64) {
        float sum = g_stats[bnIdx * 128 + t];
        float sq  = g_stats[bnIdx * 128 + 64 + t];
        float m   = sum * invn;
        float var = sq * invn - m * m;
        float sc  = gamma[t] * rsqrtf(var + 1e-5f);
        ssc[t] = sc;
        ssh[t] = beta[t] - m * sc;
        int r = r0b + t;
        ds[t] = (r < n) ? rsqrtf((float)(g_cnt[r] + 1)) : 0.f;
    }
    for (int i = t; i < 4096; i += 256) {
        int k = i >> 6, c = i & 63;
        Ws[i] = Wb ? ((c < 32) ? Wa[k * 32 + c] : Wb[k * 32 + (c - 32)]) : Wa[i];
    }
    __syncthreads();
    for (int i = t; i < 4096; i += 256) {
        int row = i >> 6, k = i & 63;
        int r = r0b + row;
        float v = 0.f;
        if (r < n) {
            v = g_B[(size_t)r * 64 + k];
            v = fmaxf(fmaf(v, ssc[k], ssh[k]), 0.f);
        }
        Xs[k * 68 + row] = v;
    }
    __syncthreads();
    const int lr = (t >> 4) * 4;
    const int c0 = (t & 15) * 4;
    float4 a0 = {0,0,0,0}, a1 = {0,0,0,0}, a2 = {0,0,0,0}, a3 = {0,0,0,0};
#pragma unroll 4
    for (int k = 0; k < 64; k++) {
        float4 xv = *(const float4*)&Xs[k * 68 + lr];
        float4 wv = *(const float4*)&Ws[k * 64 + c0];
        a0.x += xv.x * wv.x; a0.y += xv.x * wv.y; a0.z += xv.x * wv.z; a0.w += xv.x * wv.w;
        a1.x += xv.y * wv.x; a1.y += xv.y * wv.y; a1.z += xv.y * wv.z; a1.w += xv.y * wv.w;
        a2.x += xv.z * wv.x; a2.y += xv.z * wv.y; a2.z += xv.z * wv.z; a2.w += xv.z * wv.w;
        a3.x += xv.w * wv.x; a3.y += xv.w * wv.y; a3.z += xv.w * wv.z; a3.w += xv.w * wv.w;
    }
    float4 accs[4] = {a0, a1, a2, a3};
#pragma unroll
    for (int j = 0; j < 4; j++) {
        int r = r0b + lr + j;
        if (r < n) {
            float d = ds[lr + j];
            float4 o = accs[j];
            o.x *= d; o.y *= d; o.z *= d; o.w *= d;
            *(float4*)&g_A[(size_t)r * 64 + c0] = o;
        }
    }
}

// ---------------------------------------------------------------------------
// Aggregation: one warp per node, half-warp float4 gather, branch-free padded
//   inner loop (pairs always multiple of 4 -> 4 LDG.128s batch per group).
//   out[i] = dis[i]*(Ascaled[i] + sum_s Ascaled[s]) [+ bias in mode 2]
// ---------------------------------------------------------------------------
__global__ void k_agg(float* __restrict__ dout, const float* __restrict__ bias,
                      const float* __restrict__ bias2, int n, int mode) {
    const int w    = (blockIdx.x * blockDim.x + threadIdx.x) >> 5;
    const int lane = threadIdx.x & 31;
    const int hb   = lane >> 4;          // neighbor parity
    const int cg   = lane & 15;          // float4 column group
    __shared__ float ssum[64], ssq[64];
    if (mode < 2) {
        if (threadIdx.x < 64) { ssum[threadIdx.x] = 0.f; ssq[threadIdx.x] = 0.f; }
        __syncthreads();
    }
    float4 acc = {0.f, 0.f, 0.f, 0.f};
    int cntR = 0;
    const bool active = (w < n);
    if (active) {
        cntR = g_cnt[w];
        int cnt = cntR > BUCKET ? BUCKET : cntR;
        int cntp = (cnt + 7) & ~7; if (cntp > BUCKET) cntp = BUCKET;
        const size_t beg = (size_t)w * BUCKET;
        const float4* Af = (const float4*)g_A;
        int j = 0;
        while (j < cntp) {
            int m = cntp - j; if (m > 32) m = 32;    // multiple of 8
            int myS = g_srcs[beg + j + lane];        // unconditional (<= slot 95)
            int pairs = m >> 1;                      // multiple of 4
            for (int p = 0; p < pairs; p += 4) {
#pragma unroll
                for (int q = 0; q < 4; q++) {
                    int idx = 2 * (p + q) + hb;
                    int s = __shfl_sync(0xffffffffu, myS, idx);
                    float4 v = Af[(size_t)s * 16 + cg];
                    acc.x += v.x; acc.y += v.y; acc.z += v.z; acc.w += v.w;
                }
            }
            j += m;
        }
    }
    acc.x += __shfl_xor_sync(0xffffffffu, acc.x, 16);
    acc.y += __shfl_xor_sync(0xffffffffu, acc.y, 16);
    acc.z += __shfl_xor_sync(0xffffffffu, acc.z, 16);
    acc.w += __shfl_xor_sync(0xffffffffu, acc.w, 16);

    if (active && hb == 0) {
        const float di = rsqrtf((float)(cntR + 1));
        float4 self = ((const float4*)g_A)[(size_t)w * 16 + cg];
        float4 o;
        o.x = di * (acc.x + self.x);
        o.y = di * (acc.y + self.y);
        o.z = di * (acc.z + self.z);
        o.w = di * (acc.w + self.w);
        if (mode < 2) {
            ((float4*)g_B)[(size_t)w * 16 + cg] = o;
            int c = cg * 4;
            atomicAdd(&ssum[c + 0], o.x); atomicAdd(&ssq[c + 0], o.x * o.x);
            atomicAdd(&ssum[c + 1], o.y); atomicAdd(&ssq[c + 1], o.y * o.y);
            atomicAdd(&ssum[c + 2], o.z); atomicAdd(&ssq[c + 2], o.z * o.z);
            atomicAdd(&ssum[c + 3], o.w); atomicAdd(&ssq[c + 3], o.w * o.w);
        } else {
            if (cg < 8) {                // cols 0..31 -> mu
                float4 b = ((const float4*)bias)[cg];
                o.x += b.x; o.y += b.y; o.z += b.z; o.w += b.w;
                ((float4*)dout)[(size_t)w * 8 + cg] = o;
            } else {                     // cols 32..63 -> logstd
                float4 b = ((const float4*)bias2)[cg - 8];
                o.x += b.x; o.y += b.y; o.z += b.z; o.w += b.w;
                ((float4*)(dout + (size_t)n * 32))[(size_t)w * 8 + (cg - 8)] = o;
            }
        }
    }
    if (mode < 2) {
        __syncthreads();
        if (threadIdx.x < 64) {
            atomicAdd(&g_stats[mode * 128 + threadIdx.x],      ssum[threadIdx.x]);
            atomicAdd(&g_stats[mode * 128 + 64 + threadIdx.x], ssq[threadIdx.x]);
        }
    }
}

// ---------------------------------------------------------------------------
extern "C" void kernel_launch(void* const* d_in, const int* in_sizes, int n_in,
                              void* d_out, int out_size) {
    const float* x     = (const float*)d_in[0];
    const void*  ei    = d_in[1];
    const float* W1    = (const float*)d_in[2];
    const float* g1    = (const float*)d_in[4];
    const float* beta1 = (const float*)d_in[5];
    const float* W2    = (const float*)d_in[6];
    const float* g2    = (const float*)d_in[8];
    const float* beta2 = (const float*)d_in[9];
    const float* Wmu   = (const float*)d_in[10];
    const float* bmu   = (const float*)d_in[11];
    const float* Wls   = (const float*)d_in[12];
    const float* bls   = (const float*)d_in[13];
    float* out = (float*)d_out;

    const int n = in_sizes[0] / 81;
    const int E = in_sizes[1] / 2;
    const float invn = 1.0f / (float)n;

    const int TB = 256;
    const int nBlkN = (n + TB - 1) / TB;
    const int nBlkE = (E + TB - 1) / TB;
    const int nBlkG = (n + 63) / 64;
    const int nBlkW = (n + 7) / 8;       // agg: 1 warp/node, 8 warps/block

    // Graph build (one pass + pad)
    k_init<<<nBlkN, TB>>>((const unsigned*)ei, n);
    k_fill<<<nBlkE, TB>>>(ei, E);
    k_pad<<<nBlkN, TB>>>(n);

    // Layer 1
    k_gemm81<<<nBlkG, 256>>>(x, W1, n);
    k_agg<<<nBlkW, TB>>>(nullptr, nullptr, nullptr, n, 0);

    // Layer 2
    k_gemm64<<<nBlkG, 256>>>(W2, nullptr, g1, beta1, 0, n, invn);
    k_agg<<<nBlkW, TB>>>(nullptr, nullptr, nullptr, n, 1);

    // mu / logstd (fused concat weights)
    k_gemm64<<<nBlkG, 256>>>(Wmu, Wls, g2, beta2, 1, n, invn);
    k_agg<<<nBlkW, TB>>>(out, bmu, bls, n, 2);
}

// round 15
// speedup vs baseline: 1.5113x; 1.5113x over previous
#include <cuda_runtime.h>
#include <cuda_fp16.h>
#include <cstdint>
#include <cstddef>

// ============================================================================
// EnhancedGNNEncoder: 2x GCNConv(+BN+ReLU) + GCNConv mu / GCNConv logstd
//   N=100000, E=3200000, dims 81 -> 64 -> 64 -> {32|32}
// R13 = R6 (387us, best) + fp16 feature table ONLY:
//   - g_A stored as half (row = 64 halves = 128B). Agg gathers LDG.64/lane
//     (16 lanes cover a row -> 1 cache line per neighbor), fp32 accumulate.
//   - Agg loop shape is R6 EXACTLY (half-warp, unroll-4 with break) — R5/R8
//     proved restructuring this loop regresses.
//   - GEMM epilogues store half4 (uint2); everything else identical to R6.
// ============================================================================

#define MAXN 100000
#define MAXE 3200000
#define BUCKET 96

__device__ int    g_cnt[MAXN];                    // per-node degree
__device__ int    g_srcs[(size_t)MAXN * BUCKET];  // bucketed adjacency (by dst)
__device__ __half g_Ah[(size_t)(MAXN + 1) * 64];  // fp16 features; row MAXN = zeros (unused pad)
__device__ float  g_B[(size_t)MAXN * 64];         // aggregation outputs (BN inputs)
__device__ float  g_stats[2 * 128];               // per BN layer: sum(64) | sumsq(64)
__device__ int    g_is64;

// ---------------------------------------------------------------------------
// init: zero counters/stats; block 0 probes edge dtype (int64 => high words 0)
// ---------------------------------------------------------------------------
__global__ void k_init(const unsigned* __restrict__ p, int n) {
    int i = blockIdx.x * blockDim.x + threadIdx.x;
    if (i < n)   g_cnt[i] = 0;
    if (i < 256) g_stats[i] = 0.f;
    if (i < 64)  g_Ah[(size_t)MAXN * 64 + i] = __float2half(0.f);
    if (blockIdx.x == 0) {
        unsigned acc = 0;
        for (int k = threadIdx.x; k < 2048; k += 256) acc |= p[2 * k + 1];
#pragma unroll
        for (int off = 16; off; off >>= 1) acc |= __shfl_xor_sync(0xffffffffu, acc, off);
        __shared__ unsigned w[8];
        if ((threadIdx.x & 31) == 0) w[threadIdx.x >> 5] = acc;
        __syncthreads();
        if (threadIdx.x == 0) {
            unsigned t = 0;
#pragma unroll
            for (int q = 0; q < 8; q++) t |= w[q];
            g_is64 = (t == 0) ? 1 : 0;
        }
    }
}

// ---------------------------------------------------------------------------
// fill: one pass. slot = atomicAdd(cnt[dst]); srcs[dst*96+slot] = src
// ---------------------------------------------------------------------------
__global__ void k_fill(const void* __restrict__ ei, int E) {
    int e = blockIdx.x * blockDim.x + threadIdx.x;
    if (e >= E) return;
    int s, d;
    if (g_is64) {
        s = (int)((const long long*)ei)[e];
        d = (int)((const long long*)ei)[(long long)E + e];
    } else {
        s = ((const int*)ei)[e];
        d = ((const int*)ei)[E + e];
    }
    int slot = atomicAdd(&g_cnt[d], 1);
    if (slot < BUCKET) g_srcs[(size_t)d * BUCKET + slot] = s;
}

// ---------------------------------------------------------------------------
// fp16 store helper: 4 floats -> 4 halves (8B)
// ---------------------------------------------------------------------------
__device__ __forceinline__ void store_half4(size_t elem_off, float4 o) {
    __half2 h0 = __floats2half2_rn(o.x, o.y);
    __half2 h1 = __floats2half2_rn(o.z, o.w);
    uint2 u;
    u.x = *(const unsigned*)&h0;
    u.y = *(const unsigned*)&h1;
    *(uint2*)&g_Ah[elem_off] = u;
}

// ---------------------------------------------------------------------------
// GEMM1: g_Ah[r] = fp16( dis[r] * (x[r,81] @ W1[81,64]) ). 4x4 register tiling.
// ---------------------------------------------------------------------------
__global__ void k_gemm81(const float* __restrict__ x, const float* __restrict__ W, int n) {
    __shared__ float Ws[81 * 64];
    __shared__ float Xs[81 * 68];   // [k][row], stride 68
    __shared__ float ds[64];
    const int t = threadIdx.x;          // 256
    const int r0b = blockIdx.x * 64;
    for (int i = t; i < 81 * 64; i += 256) Ws[i] = W[i];
    if (t < 64) {
        int r = r0b + t;
        ds[t] = (r < n) ? rsqrtf((float)(g_cnt[r] + 1)) : 0.f;
    }
    {
        size_t gbase = (size_t)r0b * 81;
        size_t lim = (size_t)n * 81;
        for (int i = t; i < 64 * 81; i += 256) {
            size_t g = gbase + i;
            float v = (g < lim) ? x[g] : 0.f;
            int row = i / 81, k = i - row * 81;
            Xs[k * 68 + row] = v;
        }
    }
    __syncthreads();
    const int lr = (t >> 4) * 4;
    const int c0 = (t & 15) * 4;
    float4 a0 = {0,0,0,0}, a1 = {0,0,0,0}, a2 = {0,0,0,0}, a3 = {0,0,0,0};
#pragma unroll 3
    for (int k = 0; k < 81; k++) {
        float4 xv = *(const float4*)&Xs[k * 68 + lr];
        float4 wv = *(const float4*)&Ws[k * 64 + c0];
        a0.x += xv.x * wv.x; a0.y += xv.x * wv.y; a0.z += xv.x * wv.z; a0.w += xv.x * wv.w;
        a1.x += xv.y * wv.x; a1.y += xv.y * wv.y; a1.z += xv.y * wv.z; a1.w += xv.y * wv.w;
        a2.x += xv.z * wv.x; a2.y += xv.z * wv.y; a2.z += xv.z * wv.z; a2.w += xv.z * wv.w;
        a3.x += xv.w * wv.x; a3.y += xv.w * wv.y; a3.z += xv.w * wv.z; a3.w += xv.w * wv.w;
    }
    float4 accs[4] = {a0, a1, a2, a3};
#pragma unroll
    for (int j = 0; j < 4; j++) {
        int r = r0b + lr + j;
        if (r < n) {
            float d = ds[lr + j];
            float4 o = accs[j];
            o.x *= d; o.y *= d; o.z *= d; o.w *= d;
            store_half4((size_t)r * 64 + c0, o);
        }
    }
}

// ---------------------------------------------------------------------------
// GEMM64: g_Ah[r] = fp16( dis[r] * (BNReLU(g_B)[r,64] @ W[64,64]) )
// ---------------------------------------------------------------------------
__global__ void k_gemm64(const float* __restrict__ Wa, const float* __restrict__ Wb,
                         const float* __restrict__ gamma, const float* __restrict__ beta,
                         int bnIdx, int n, float invn) {
    __shared__ float Ws[64 * 64];
    __shared__ float Xs[64 * 68];
    __shared__ float ssc[64], ssh[64], ds[64];
    const int t = threadIdx.x;          // 256
    const int r0b = blockIdx.x * 64;
    if (t < 64) {
        float sum = g_stats[bnIdx * 128 + t];
        float sq  = g_stats[bnIdx * 128 + 64 + t];
        float m   = sum * invn;
        float var = sq * invn - m * m;
        float sc  = gamma[t] * rsqrtf(var + 1e-5f);
        ssc[t] = sc;
        ssh[t] = beta[t] - m * sc;
        int r = r0b + t;
        ds[t] = (r < n) ? rsqrtf((float)(g_cnt[r] + 1)) : 0.f;
    }
    for (int i = t; i < 4096; i += 256) {
        int k = i >> 6, c = i & 63;
        Ws[i] = Wb ? ((c < 32) ? Wa[k * 32 + c] : Wb[k * 32 + (c - 32)]) : Wa[i];
    }
    __syncthreads();
    for (int i = t; i < 4096; i += 256) {
        int row = i >> 6, k = i & 63;
        int r = r0b + row;
        float v = 0.f;
        if (r < n) {
            v = g_B[(size_t)r * 64 + k];
            v = fmaxf(fmaf(v, ssc[k], ssh[k]), 0.f);
        }
        Xs[k * 68 + row] = v;
    }
    __syncthreads();
    const int lr = (t >> 4) * 4;
    const int c0 = (t & 15) * 4;
    float4 a0 = {0,0,0,0}, a1 = {0,0,0,0}, a2 = {0,0,0,0}, a3 = {0,0,0,0};
#pragma unroll 4
    for (int k = 0; k < 64; k++) {
        float4 xv = *(const float4*)&Xs[k * 68 + lr];
        float4 wv = *(const float4*)&Ws[k * 64 + c0];
        a0.x += xv.x * wv.x; a0.y += xv.x * wv.y; a0.z += xv.x * wv.z; a0.w += xv.x * wv.w;
        a1.x += xv.y * wv.x; a1.y += xv.y * wv.y; a1.z += xv.y * wv.z; a1.w += xv.y * wv.w;
        a2.x += xv.z * wv.x; a2.y += xv.z * wv.y; a2.z += xv.z * wv.z; a2.w += xv.z * wv.w;
        a3.x += xv.w * wv.x; a3.y += xv.w * wv.y; a3.z += xv.w * wv.z; a3.w += xv.w * wv.w;
    }
    float4 accs[4] = {a0, a1, a2, a3};
#pragma unroll
    for (int j = 0; j < 4; j++) {
        int r = r0b + lr + j;
        if (r < n) {
            float d = ds[lr + j];
            float4 o = accs[j];
            o.x *= d; o.y *= d; o.z *= d; o.w *= d;
            store_half4((size_t)r * 64 + c0, o);
        }
    }
}

// ---------------------------------------------------------------------------
// Aggregation (R6 loop shape EXACTLY): one warp per node, half-warp gather,
//   2 neighbors/iter, unroll-4-with-break, butterfly xor16, smem BN stats.
//   Only change: rows are fp16 (LDG.64/lane -> 128B line per neighbor),
//   converted to fp32 before accumulate.
// ---------------------------------------------------------------------------
__global__ void k_agg(float* __restrict__ dout, const float* __restrict__ bias,
                      const float* __restrict__ bias2, int n, int mode) {
    const int w    = (blockIdx.x * blockDim.x + threadIdx.x) >> 5;
    const int lane = threadIdx.x & 31;
    const int hb   = lane >> 4;          // neighbor parity
    const int cg   = lane & 15;          // 8B column group (4 halves)
    __shared__ float ssum[64], ssq[64];
    if (mode < 2) {
        if (threadIdx.x < 64) { ssum[threadIdx.x] = 0.f; ssq[threadIdx.x] = 0.f; }
        __syncthreads();
    }
    float4 acc = {0.f, 0.f, 0.f, 0.f};
    int cnt = 0;
    const bool active = (w < n);
    if (active) {
        cnt = g_cnt[w]; if (cnt > BUCKET) cnt = BUCKET;
        const size_t beg = (size_t)w * BUCKET;
        const uint2* Af = (const uint2*)g_Ah;
        int j = 0;
        while (j < cnt) {
            int m = cnt - j; if (m > 32) m = 32;
            int myS = (lane < m) ? g_srcs[beg + j + lane] : 0;
#pragma unroll 4
            for (int p = 0; p < 16; p++) {
                if (2 * p >= m) break;
                int idx = 2 * p + hb;
                int s = __shfl_sync(0xffffffffu, myS, idx);
                if (idx < m) {
                    uint2 u = Af[(size_t)s * 16 + cg];
                    float2 f0 = __half22float2(*(const __half2*)&u.x);
                    float2 f1 = __half22float2(*(const __half2*)&u.y);
                    acc.x += f0.x; acc.y += f0.y; acc.z += f1.x; acc.w += f1.y;
                }
            }
            j += m;
        }
    }
    acc.x += __shfl_xor_sync(0xffffffffu, acc.x, 16);
    acc.y += __shfl_xor_sync(0xffffffffu, acc.y, 16);
    acc.z += __shfl_xor_sync(0xffffffffu, acc.z, 16);
    acc.w += __shfl_xor_sync(0xffffffffu, acc.w, 16);

    if (active && hb == 0) {
        const float di = rsqrtf((float)(cnt + 1));
        uint2 su = ((const uint2*)g_Ah)[(size_t)w * 16 + cg];
        float2 s0 = __half22float2(*(const __half2*)&su.x);
        float2 s1 = __half22float2(*(const __half2*)&su.y);
        float4 o;
        o.x = di * (acc.x + s0.x);
        o.y = di * (acc.y + s0.y);
        o.z = di * (acc.z + s1.x);
        o.w = di * (acc.w + s1.y);
        if (mode < 2) {
            *(float4*)&g_B[(size_t)w * 64 + cg * 4] = o;
            int c = cg * 4;
            atomicAdd(&ssum[c + 0], o.x); atomicAdd(&ssq[c + 0], o.x * o.x);
            atomicAdd(&ssum[c + 1], o.y); atomicAdd(&ssq[c + 1], o.y * o.y);
            atomicAdd(&ssum[c + 2], o.z); atomicAdd(&ssq[c + 2], o.z * o.z);
            atomicAdd(&ssum[c + 3], o.w); atomicAdd(&ssq[c + 3], o.w * o.w);
        } else {
            if (cg < 8) {                // cols 0..31 -> mu
                float4 b = ((const float4*)bias)[cg];
                o.x += b.x; o.y += b.y; o.z += b.z; o.w += b.w;
                ((float4*)dout)[(size_t)w * 8 + cg] = o;
            } else {                     // cols 32..63 -> logstd
                float4 b = ((const float4*)bias2)[cg - 8];
                o.x += b.x; o.y += b.y; o.z += b.z; o.w += b.w;
                ((float4*)(dout + (size_t)n * 32))[(size_t)w * 8 + (cg - 8)] = o;
            }
        }
    }
    if (mode < 2) {
        __syncthreads();
        if (threadIdx.x < 64) {
            atomicAdd(&g_stats[mode * 128 + threadIdx.x],      ssum[threadIdx.x]);
            atomicAdd(&g_stats[mode * 128 + 64 + threadIdx.x], ssq[threadIdx.x]);
        }
    }
}

// ---------------------------------------------------------------------------
extern "C" void kernel_launch(void* const* d_in, const int* in_sizes, int n_in,
                              void* d_out, int out_size) {
    const float* x     = (const float*)d_in[0];
    const void*  ei    = d_in[1];
    const float* W1    = (const float*)d_in[2];
    const float* g1    = (const float*)d_in[4];
    const float* beta1 = (const float*)d_in[5];
    const float* W2    = (const float*)d_in[6];
    const float* g2    = (const float*)d_in[8];
    const float* beta2 = (const float*)d_in[9];
    const float* Wmu   = (const float*)d_in[10];
    const float* bmu   = (const float*)d_in[11];
    const float* Wls   = (const float*)d_in[12];
    const float* bls   = (const float*)d_in[13];
    float* out = (float*)d_out;

    const int n = in_sizes[0] / 81;
    const int E = in_sizes[1] / 2;
    const float invn = 1.0f / (float)n;

    const int TB = 256;
    const int nBlkN = (n + TB - 1) / TB;
    const int nBlkE = (E + TB - 1) / TB;
    const int nBlkG = (n + 63) / 64;
    const int nBlkW = (n + 7) / 8;       // agg: 1 warp/node, 8 warps/block

    // Graph build (one pass)
    k_init<<<nBlkN, TB>>>((const unsigned*)ei, n);
    k_fill<<<nBlkE, TB>>>(ei, E);

    // Layer 1
    k_gemm81<<<nBlkG, 256>>>(x, W1, n);
    k_agg<<<nBlkW, TB>>>(nullptr, nullptr, nullptr, n, 0);

    // Layer 2
    k_gemm64<<<nBlkG, 256>>>(W2, nullptr, g1, beta1, 0, n, invn);
    k_agg<<<nBlkW, TB>>>(nullptr, nullptr, nullptr, n, 1);

    // mu / logstd (fused concat weights)
    k_gemm64<<<nBlkG, 256>>>(Wmu, Wls, g2, beta2, 1, n, invn);
    k_agg<<<nBlkW, TB>>>(out, bmu, bls, n, 2);
}

// round 16
// speedup vs baseline: 1.5208x; 1.0063x over previous
#include <cuda_runtime.h>
#include <cuda_fp16.h>
#include <cstdint>
#include <cstddef>

// ============================================================================
// EnhancedGNNEncoder: 2x GCNConv(+BN+ReLU) + GCNConv mu / GCNConv logstd
//   N=100000, E=3200000, dims 81 -> 64 -> 64 -> {32|32}
// R15 = R13 (380us, best) with ONE change: agg inner gather loop unroll 4 -> 8
//   (MLP 4 -> 8; agg is latency-throughput matched at MLP 4 per the R13
//   profile: occ 94%, issue 59%, L1 46% -- all sub-cap).
// ============================================================================

#define MAXN 100000
#define MAXE 3200000
#define BUCKET 96

__device__ int    g_cnt[MAXN];                    // per-node degree
__device__ int    g_srcs[(size_t)MAXN * BUCKET];  // bucketed adjacency (by dst)
__device__ __half g_Ah[(size_t)(MAXN + 1) * 64];  // fp16 features
__device__ float  g_B[(size_t)MAXN * 64];         // aggregation outputs (BN inputs)
__device__ float  g_stats[2 * 128];               // per BN layer: sum(64) | sumsq(64)
__device__ int    g_is64;

// ---------------------------------------------------------------------------
// init: zero counters/stats; block 0 probes edge dtype (int64 => high words 0)
// ---------------------------------------------------------------------------
__global__ void k_init(const unsigned* __restrict__ p, int n) {
    int i = blockIdx.x * blockDim.x + threadIdx.x;
    if (i < n)   g_cnt[i] = 0;
    if (i < 256) g_stats[i] = 0.f;
    if (i < 64)  g_Ah[(size_t)MAXN * 64 + i] = __float2half(0.f);
    if (blockIdx.x == 0) {
        unsigned acc = 0;
        for (int k = threadIdx.x; k < 2048; k += 256) acc |= p[2 * k + 1];
#pragma unroll
        for (int off = 16; off; off >>= 1) acc |= __shfl_xor_sync(0xffffffffu, acc, off);
        __shared__ unsigned w[8];
        if ((threadIdx.x & 31) == 0) w[threadIdx.x >> 5] = acc;
        __syncthreads();
        if (threadIdx.x == 0) {
            unsigned t = 0;
#pragma unroll
            for (int q = 0; q < 8; q++) t |= w[q];
            g_is64 = (t == 0) ? 1 : 0;
        }
    }
}

// ---------------------------------------------------------------------------
// fill: one pass. slot = atomicAdd(cnt[dst]); srcs[dst*96+slot] = src
// ---------------------------------------------------------------------------
__global__ void k_fill(const void* __restrict__ ei, int E) {
    int e = blockIdx.x * blockDim.x + threadIdx.x;
    if (e >= E) return;
    int s, d;
    if (g_is64) {
        s = (int)((const long long*)ei)[e];
        d = (int)((const long long*)ei)[(long long)E + e];
    } else {
        s = ((const int*)ei)[e];
        d = ((const int*)ei)[E + e];
    }
    int slot = atomicAdd(&g_cnt[d], 1);
    if (slot < BUCKET) g_srcs[(size_t)d * BUCKET + slot] = s;
}

// ---------------------------------------------------------------------------
// fp16 store helper: 4 floats -> 4 halves (8B)
// ---------------------------------------------------------------------------
__device__ __forceinline__ void store_half4(size_t elem_off, float4 o) {
    __half2 h0 = __floats2half2_rn(o.x, o.y);
    __half2 h1 = __floats2half2_rn(o.z, o.w);
    uint2 u;
    u.x = *(const unsigned*)&h0;
    u.y = *(const unsigned*)&h1;
    *(uint2*)&g_Ah[elem_off] = u;
}

// ---------------------------------------------------------------------------
// GEMM1: g_Ah[r] = fp16( dis[r] * (x[r,81] @ W1[81,64]) ). 4x4 register tiling.
// ---------------------------------------------------------------------------
__global__ void k_gemm81(const float* __restrict__ x, const float* __restrict__ W, int n) {
    __shared__ float Ws[81 * 64];
    __shared__ float Xs[81 * 68];   // [k][row], stride 68
    __shared__ float ds[64];
    const int t = threadIdx.x;          // 256
    const int r0b = blockIdx.x * 64;
    for (int i = t; i < 81 * 64; i += 256) Ws[i] = W[i];
    if (t < 64) {
        int r = r0b + t;
        ds[t] = (r < n) ? rsqrtf((float)(g_cnt[r] + 1)) : 0.f;
    }
    {
        size_t gbase = (size_t)r0b * 81;
        size_t lim = (size_t)n * 81;
        for (int i = t; i < 64 * 81; i += 256) {
            size_t g = gbase + i;
            float v = (g < lim) ? x[g] : 0.f;
            int row = i / 81, k = i - row * 81;
            Xs[k * 68 + row] = v;
        }
    }
    __syncthreads();
    const int lr = (t >> 4) * 4;
    const int c0 = (t & 15) * 4;
    float4 a0 = {0,0,0,0}, a1 = {0,0,0,0}, a2 = {0,0,0,0}, a3 = {0,0,0,0};
#pragma unroll 3
    for (int k = 0; k < 81; k++) {
        float4 xv = *(const float4*)&Xs[k * 68 + lr];
        float4 wv = *(const float4*)&Ws[k * 64 + c0];
        a0.x += xv.x * wv.x; a0.y += xv.x * wv.y; a0.z += xv.x * wv.z; a0.w += xv.x * wv.w;
        a1.x += xv.y * wv.x; a1.y += xv.y * wv.y; a1.z += xv.y * wv.z; a1.w += xv.y * wv.w;
        a2.x += xv.z * wv.x; a2.y += xv.z * wv.y; a2.z += xv.z * wv.z; a2.w += xv.z * wv.w;
        a3.x += xv.w * wv.x; a3.y += xv.w * wv.y; a3.z += xv.w * wv.z; a3.w += xv.w * wv.w;
    }
    float4 accs[4] = {a0, a1, a2, a3};
#pragma unroll
    for (int j = 0; j < 4; j++) {
        int r = r0b + lr + j;
        if (r < n) {
            float d = ds[lr + j];
            float4 o = accs[j];
            o.x *= d; o.y *= d; o.z *= d; o.w *= d;
            store_half4((size_t)r * 64 + c0, o);
        }
    }
}

// ---------------------------------------------------------------------------
// GEMM64: g_Ah[r] = fp16( dis[r] * (BNReLU(g_B)[r,64] @ W[64,64]) )
// ---------------------------------------------------------------------------
__global__ void k_gemm64(const float* __restrict__ Wa, const float* __restrict__ Wb,
                         const float* __restrict__ gamma, const float* __restrict__ beta,
                         int bnIdx, int n, float invn) {
    __shared__ float Ws[64 * 64];
    __shared__ float Xs[64 * 68];
    __shared__ float ssc[64], ssh[64], ds[64];
    const int t = threadIdx.x;          // 256
    const int r0b = blockIdx.x * 64;
    if (t < 64) {
        float sum = g_stats[bnIdx * 128 + t];
        float sq  = g_stats[bnIdx * 128 + 64 + t];
        float m   = sum * invn;
        float var = sq * invn - m * m;
        float sc  = gamma[t] * rsqrtf(var + 1e-5f);
        ssc[t] = sc;
        ssh[t] = beta[t] - m * sc;
        int r = r0b + t;
        ds[t] = (r < n) ? rsqrtf((float)(g_cnt[r] + 1)) : 0.f;
    }
    for (int i = t; i < 4096; i += 256) {
        int k = i >> 6, c = i & 63;
        Ws[i] = Wb ? ((c < 32) ? Wa[k * 32 + c] : Wb[k * 32 + (c - 32)]) : Wa[i];
    }
    __syncthreads();
    for (int i = t; i < 4096; i += 256) {
        int row = i >> 6, k = i & 63;
        int r = r0b + row;
        float v = 0.f;
        if (r < n) {
            v = g_B[(size_t)r * 64 + k];
            v = fmaxf(fmaf(v, ssc[k], ssh[k]), 0.f);
        }
        Xs[k * 68 + row] = v;
    }
    __syncthreads();
    const int lr = (t >> 4) * 4;
    const int c0 = (t & 15) * 4;
    float4 a0 = {0,0,0,0}, a1 = {0,0,0,0}, a2 = {0,0,0,0}, a3 = {0,0,0,0};
#pragma unroll 4
    for (int k = 0; k < 64; k++) {
        float4 xv = *(const float4*)&Xs[k * 68 + lr];
        float4 wv = *(const float4*)&Ws[k * 64 + c0];
        a0.x += xv.x * wv.x; a0.y += xv.x * wv.y; a0.z += xv.x * wv.z; a0.w += xv.x * wv.w;
        a1.x += xv.y * wv.x; a1.y += xv.y * wv.y; a1.z += xv.y * wv.z; a1.w += xv.y * wv.w;
        a2.x += xv.z * wv.x; a2.y += xv.z * wv.y; a2.z += xv.z * wv.z; a2.w += xv.z * wv.w;
        a3.x += xv.w * wv.x; a3.y += xv.w * wv.y; a3.z += xv.w * wv.z; a3.w += xv.w * wv.w;
    }
    float4 accs[4] = {a0, a1, a2, a3};
#pragma unroll
    for (int j = 0; j < 4; j++) {
        int r = r0b + lr + j;
        if (r < n) {
            float d = ds[lr + j];
            float4 o = accs[j];
            o.x *= d; o.y *= d; o.z *= d; o.w *= d;
            store_half4((size_t)r * 64 + c0, o);
        }
    }
}

// ---------------------------------------------------------------------------
// Aggregation (R13 exactly, except inner unroll 4 -> 8): one warp per node,
//   half-warp fp16 gather (LDG.64/lane), fp32 accumulate, butterfly xor16,
//   smem BN stats.
// ---------------------------------------------------------------------------
__global__ void k_agg(float* __restrict__ dout, const float* __restrict__ bias,
                      const float* __restrict__ bias2, int n, int mode) {
    const int w    = (blockIdx.x * blockDim.x + threadIdx.x) >> 5;
    const int lane = threadIdx.x & 31;
    const int hb   = lane >> 4;          // neighbor parity
    const int cg   = lane & 15;          // 8B column group (4 halves)
    __shared__ float ssum[64], ssq[64];
    if (mode < 2) {
        if (threadIdx.x < 64) { ssum[threadIdx.x] = 0.f; ssq[threadIdx.x] = 0.f; }
        __syncthreads();
    }
    float4 acc = {0.f, 0.f, 0.f, 0.f};
    int cnt = 0;
    const bool active = (w < n);
    if (active) {
        cnt = g_cnt[w]; if (cnt > BUCKET) cnt = BUCKET;
        const size_t beg = (size_t)w * BUCKET;
        const uint2* Af = (const uint2*)g_Ah;
        int j = 0;
        while (j < cnt) {
            int m = cnt - j; if (m > 32) m = 32;
            int myS = (lane < m) ? g_srcs[beg + j + lane] : 0;
#pragma unroll 8
            for (int p = 0; p < 16; p++) {
                if (2 * p >= m) break;
                int idx = 2 * p + hb;
                int s = __shfl_sync(0xffffffffu, myS, idx);
                if (idx < m) {
                    uint2 u = Af[(size_t)s * 16 + cg];
                    float2 f0 = __half22float2(*(const __half2*)&u.x);
                    float2 f1 = __half22float2(*(const __half2*)&u.y);
                    acc.x += f0.x; acc.y += f0.y; acc.z += f1.x; acc.w += f1.y;
                }
            }
            j += m;
        }
    }
    acc.x += __shfl_xor_sync(0xffffffffu, acc.x, 16);
    acc.y += __shfl_xor_sync(0xffffffffu, acc.y, 16);
    acc.z += __shfl_xor_sync(0xffffffffu, acc.z, 16);
    acc.w += __shfl_xor_sync(0xffffffffu, acc.w, 16);

    if (active && hb == 0) {
        const float di = rsqrtf((float)(cnt + 1));
        uint2 su = ((const uint2*)g_Ah)[(size_t)w * 16 + cg];
        float2 s0 = __half22float2(*(const __half2*)&su.x);
        float2 s1 = __half22float2(*(const __half2*)&su.y);
        float4 o;
        o.x = di * (acc.x + s0.x);
        o.y = di * (acc.y + s0.y);
        o.z = di * (acc.z + s1.x);
        o.w = di * (acc.w + s1.y);
        if (mode < 2) {
            *(float4*)&g_B[(size_t)w * 64 + cg * 4] = o;
            int c = cg * 4;
            atomicAdd(&ssum[c + 0], o.x); atomicAdd(&ssq[c + 0], o.x * o.x);
            atomicAdd(&ssum[c + 1], o.y); atomicAdd(&ssq[c + 1], o.y * o.y);
            atomicAdd(&ssum[c + 2], o.z); atomicAdd(&ssq[c + 2], o.z * o.z);
            atomicAdd(&ssum[c + 3], o.w); atomicAdd(&ssq[c + 3], o.w * o.w);
        } else {
            if (cg < 8) {                // cols 0..31 -> mu
                float4 b = ((const float4*)bias)[cg];
                o.x += b.x; o.y += b.y; o.z += b.z; o.w += b.w;
                ((float4*)dout)[(size_t)w * 8 + cg] = o;
            } else {                     // cols 32..63 -> logstd
                float4 b = ((const float4*)bias2)[cg - 8];
                o.x += b.x; o.y += b.y; o.z += b.z; o.w += b.w;
                ((float4*)(dout + (size_t)n * 32))[(size_t)w * 8 + (cg - 8)] = o;
            }
        }
    }
    if (mode < 2) {
        __syncthreads();
        if (threadIdx.x < 64) {
            atomicAdd(&g_stats[mode * 128 + threadIdx.x],      ssum[threadIdx.x]);
            atomicAdd(&g_stats[mode * 128 + 64 + threadIdx.x], ssq[threadIdx.x]);
        }
    }
}

// ---------------------------------------------------------------------------
extern "C" void kernel_launch(void* const* d_in, const int* in_sizes, int n_in,
                              void* d_out, int out_size) {
    const float* x     = (const float*)d_in[0];
    const void*  ei    = d_in[1];
    const float* W1    = (const float*)d_in[2];
    const float* g1    = (const float*)d_in[4];
    const float* beta1 = (const float*)d_in[5];
    const float* W2    = (const float*)d_in[6];
    const float* g2    = (const float*)d_in[8];
    const float* beta2 = (const float*)d_in[9];
    const float* Wmu   = (const float*)d_in[10];
    const float* bmu   = (const float*)d_in[11];
    const float* Wls   = (const float*)d_in[12];
    const float* bls   = (const float*)d_in[13];
    float* out = (float*)d_out;

    const int n = in_sizes[0] / 81;
    const int E = in_sizes[1] / 2;
    const float invn = 1.0f / (float)n;

    const int TB = 256;
    const int nBlkN = (n + TB - 1) / TB;
    const int nBlkE = (E + TB - 1) / TB;
    const int nBlkG = (n + 63) / 64;
    const int nBlkW = (n + 7) / 8;       // agg: 1 warp/node, 8 warps/block

    // Graph build (one pass)
    k_init<<<nBlkN, TB>>>((const unsigned*)ei, n);
    k_fill<<<nBlkE, TB>>>(ei, E);

    // Layer 1
    k_gemm81<<<nBlkG, 256>>>(x, W1, n);
    k_agg<<<nBlkW, TB>>>(nullptr, nullptr, nullptr, n, 0);

    // Layer 2
    k_gemm64<<<nBlkG, 256>>>(W2, nullptr, g1, beta1, 0, n, invn);
    k_agg<<<nBlkW, TB>>>(nullptr, nullptr, nullptr, n, 1);

    // mu / logstd (fused concat weights)
    k_gemm64<<<nBlkG, 256>>>(Wmu, Wls, g2, beta2, 1, n, invn);
    k_agg<<<nBlkW, TB>>>(out, bmu, bls, n, 2);
}